// round 1
// baseline (speedup 1.0000x reference)
#include <cuda_runtime.h>
#include <cstdint>
#include <math_constants.h>

#define NN   4096
#define FIN  128
#define NH   8
#define FO   64
#define FTOT 512
#define TI   64
#define TJ   128

// scratch (static device allocations only — no cudaMalloc allowed)
__device__ float g_ht[NN * FTOT];     // 8 MB: hW row-major == ht flat (h,n,o)
__device__ float g_src[NH * NN];
__device__ float g_m[NH * NN];
__device__ float g_tgtT[NN * NH];     // transposed for coalesced per-j access

// ---------- packed f32x2 helpers (Blackwell) ----------
__device__ __forceinline__ unsigned long long pack2(float x, float y) {
    unsigned long long r;
    asm("mov.b64 %0, {%1, %2};" : "=l"(r) : "f"(x), "f"(y));
    return r;
}
__device__ __forceinline__ void unpack2(unsigned long long v, float& x, float& y) {
    asm("mov.b64 {%0, %1}, %2;" : "=f"(x), "=f"(y) : "l"(v));
}
// d = a*b + c  (two fp32 lanes packed in b64)
__device__ __forceinline__ unsigned long long ffma2(unsigned long long a,
                                                    unsigned long long b,
                                                    unsigned long long c) {
    unsigned long long d;
    asm("fma.rn.f32x2 %0, %1, %2, %3;" : "=l"(d) : "l"(a), "l"(b), "l"(c));
    return d;
}

// ---------- kernel A: hW = h @ W  (4096x128 @ 128x512) ----------
__global__ void k_gemm(const float* __restrict__ H, const float* __restrict__ W) {
    __shared__ float sA[32][FIN + 4];   // pad to kill bank conflicts
    __shared__ float sW[FIN][64];
    const int rt = blockIdx.x;          // 0..127
    const int ct = blockIdx.y;          // 0..7
    const int t  = threadIdx.x;         // 256
    const int row0 = rt * 32;
    const int col0 = ct * 64;

    const float4* Hv = (const float4*)(H + (size_t)row0 * FIN);
#pragma unroll
    for (int s = 0; s < 4; ++s) {
        int idx = t + 256 * s;          // float4 index; 32 f4 per row
        float4 v = Hv[idx];
        int r = idx >> 5, q = idx & 31;
        sA[r][q * 4 + 0] = v.x; sA[r][q * 4 + 1] = v.y;
        sA[r][q * 4 + 2] = v.z; sA[r][q * 4 + 3] = v.w;
    }
#pragma unroll
    for (int s = 0; s < 8; ++s) {
        int idx = t + 256 * s;          // 16 f4 per k-row
        int k = idx >> 4, q = idx & 15;
        float4 v = *(const float4*)(W + (size_t)k * FTOT + col0 + q * 4);
        *(float4*)&sW[k][q * 4] = v;
    }
    __syncthreads();

    const int r  = t >> 3;              // 0..31
    const int c0 = (t & 7) * 8;         // 0..56
    float acc[8];
#pragma unroll
    for (int c = 0; c < 8; ++c) acc[c] = 0.f;
#pragma unroll
    for (int k = 0; k < FIN; ++k) {
        float av = sA[r][k];
#pragma unroll
        for (int c = 0; c < 8; ++c) acc[c] = fmaf(av, sW[k][c0 + c], acc[c]);
    }
    float* outp = g_ht + (size_t)(row0 + r) * FTOT + col0 + c0;
    *(float4*)(outp)     = make_float4(acc[0], acc[1], acc[2], acc[3]);
    *(float4*)(outp + 4) = make_float4(acc[4], acc[5], acc[6], acc[7]);
}

// ---------- kernel B: src/tgt projections ----------
__global__ void k_srctgt(const float* __restrict__ a) {
    const int warp = threadIdx.x >> 5, lane = threadIdx.x & 31;
    const int gw = blockIdx.x * 8 + warp;      // 0..32767
    const int h = gw >> 12;
    const int n = gw & (NN - 1);
    const float* htp = g_ht + (size_t)h * (NN * FO) + (size_t)n * FO;
    float v0 = htp[lane], v1 = htp[lane + 32];
    float a0 = a[h * 128 + lane],      a1 = a[h * 128 + lane + 32];
    float b0 = a[h * 128 + 64 + lane], b1 = a[h * 128 + 96 + lane];
    float s  = v0 * a0 + v1 * a1;
    float tg = v0 * b0 + v1 * b1;
#pragma unroll
    for (int off = 16; off; off >>= 1) {
        s  += __shfl_down_sync(0xFFFFFFFFu, s, off);
        tg += __shfl_down_sync(0xFFFFFFFFu, tg, off);
    }
    if (lane == 0) {
        g_src[h * NN + n] = s;
        g_tgtT[n * NH + h] = tg;
    }
}

// ---------- kernel C1: masked row max -> m[h][i] = leaky(src_i + max_adj tgt_j) ----------
__global__ void k_maxm(const int* __restrict__ adj) {
    const int i = blockIdx.x;
    const int t = threadIdx.x;          // 256
    float mx[8];
#pragma unroll
    for (int h = 0; h < 8; ++h) mx[h] = -CUDART_INF_F;
    const int* arow = adj + (size_t)i * NN;
    for (int j = t; j < NN; j += 256) {
        if (arow[j]) {
            const float4* tp = (const float4*)(g_tgtT + j * 8);
            float4 t0 = tp[0], t1 = tp[1];
            mx[0] = fmaxf(mx[0], t0.x); mx[1] = fmaxf(mx[1], t0.y);
            mx[2] = fmaxf(mx[2], t0.z); mx[3] = fmaxf(mx[3], t0.w);
            mx[4] = fmaxf(mx[4], t1.x); mx[5] = fmaxf(mx[5], t1.y);
            mx[6] = fmaxf(mx[6], t1.z); mx[7] = fmaxf(mx[7], t1.w);
        }
    }
    __shared__ float sm[8][256];
#pragma unroll
    for (int h = 0; h < 8; ++h) sm[h][t] = mx[h];
    __syncthreads();
    for (int str = 128; str > 0; str >>= 1) {
        if (t < str) {
#pragma unroll
            for (int h = 0; h < 8; ++h)
                sm[h][t] = fmaxf(sm[h][t], sm[h][t + str]);
        }
        __syncthreads();
    }
    if (t < 8) {
        float T = sm[t][0];
        float m;
        if (T == -CUDART_INF_F) {
            m = 0.f;                    // unreachable for random dense adj
        } else {
            float e = g_src[t * NN + i] + T;
            m = (e > 0.f) ? e : 0.2f * e;
        }
        g_m[t * NN + i] = m;
    }
}

// ---------- kernel C2: fused masked-softmax-weight GEMM ----------
// block = (head, i-tile of 64 rows); streams j in tiles of 128.
// phase 1: 256 threads compute w[jj][i] = adj ? exp(leaky(src+tgt)-m) : 0 into smem
// phase 2: 256 threads = 64 o-cols x 4 row-groups; 16 fp32 accs as 8 f32x2.
__global__ void __launch_bounds__(256, 4)
k_attn(const int* __restrict__ adj, float* __restrict__ out) {
    const int head  = blockIdx.x;       // 0..7 (fastest -> adj tile shared in L2)
    const int it    = blockIdx.y;       // 0..63
    const int ibase = it * TI;
    const int t     = threadIdx.x;

    __shared__ float sw[TJ * TI];       // 32 KB

    // phase-1 identity: fixed row i1, j-group jg
    const int i1 = t >> 2;              // 0..63
    const int jg = t & 3;               // 0..3
    const float srcv = g_src[head * NN + ibase + i1];
    const float mv   = g_m[head * NN + ibase + i1];
    const int4* arow = (const int4*)(adj + (size_t)(ibase + i1) * NN);
    float spart = 0.f;

    // phase-2 identity
    const int o  = t & 63;
    const int ig = t >> 6;              // 0..3 -> rows ig*16..+15
    const float* htbase = g_ht + (size_t)head * (NN * FO) + o;
    unsigned long long acc[8];
#pragma unroll
    for (int p = 0; p < 8; ++p) acc[p] = 0ull;

    for (int jt = 0; jt < NN / TJ; ++jt) {
        const int j0 = jt * TJ;
        // ---- phase 1: weights into smem ----
#pragma unroll
        for (int k = 0; k < 8; ++k) {
            int jj = jg * 4 + k * 16;                    // local int4 start
            int4 av = arow[(j0 >> 2) + jg + k * 4];
            int aa[4] = {av.x, av.y, av.z, av.w};
#pragma unroll
            for (int d = 0; d < 4; ++d) {
                float tg = __ldg(&g_tgtT[(size_t)(j0 + jj + d) * 8 + head]);
                float e = srcv + tg;
                e = (e > 0.f) ? e : 0.2f * e;
                float wv = aa[d] ? __expf(e - mv) : 0.f;
                sw[(jj + d) * TI + i1] = wv;
                spart += wv;
            }
        }
        __syncthreads();
        // ---- phase 2: packed-f32x2 accumulation ----
        const float* htp = htbase + (size_t)j0 * FO;
#pragma unroll 4
        for (int jj = 0; jj < TJ; ++jj) {
            float b = htp[(size_t)jj * FO];
            unsigned long long bb = pack2(b, b);
            const ulonglong2* wrow = (const ulonglong2*)(sw + jj * TI + ig * 16);
#pragma unroll
            for (int p = 0; p < 4; ++p) {
                ulonglong2 q = wrow[p];
                acc[2 * p]     = ffma2(q.x, bb, acc[2 * p]);
                acc[2 * p + 1] = ffma2(q.y, bb, acc[2 * p + 1]);
            }
        }
        __syncthreads();
    }

    // ---- denominator reduction (reuse sw) ----
    sw[i1 * 4 + jg] = spart;
    __syncthreads();

#pragma unroll
    for (int p = 0; p < 8; ++p) {
        int r0 = ig * 16 + 2 * p;
        float x, y;
        unpack2(acc[p], x, y);
        float s0 = sw[r0 * 4 + 0] + sw[r0 * 4 + 1] + sw[r0 * 4 + 2] + sw[r0 * 4 + 3];
        float s1 = sw[(r0 + 1) * 4 + 0] + sw[(r0 + 1) * 4 + 1] +
                   sw[(r0 + 1) * 4 + 2] + sw[(r0 + 1) * 4 + 3];
        float o0 = (s0 > 0.f) ? x / s0 : 0.f;
        float o1 = (s1 > 0.f) ? y / s1 : 0.f;
        size_t base = (size_t)head * (NN * FO) + (size_t)(ibase + r0) * FO + o;
        out[base]      = o0;
        out[base + FO] = o1;
    }
}

extern "C" void kernel_launch(void* const* d_in, const int* in_sizes, int n_in,
                              void* d_out, int out_size) {
    // identify inputs defensively by element count (all distinct)
    const float* H = nullptr; const int* adj = nullptr;
    const float* W = nullptr; const float* a = nullptr;
    for (int i = 0; i < n_in; ++i) {
        switch (in_sizes[i]) {
            case NN * FIN:      H   = (const float*)d_in[i]; break;   // 524288
            case NN * NN:       adj = (const int*)d_in[i];   break;   // 16777216
            case FIN * FTOT:    W   = (const float*)d_in[i]; break;   // 65536
            case NH * 2 * FO:   a   = (const float*)d_in[i]; break;   // 1024
        }
    }
    float* out = (float*)d_out;

    k_gemm  <<<dim3(128, 8), 256>>>(H, W);
    k_srctgt<<<(NN * NH) / 8, 256>>>(a);
    k_maxm  <<<NN, 256>>>(adj);
    k_attn  <<<dim3(NH, NN / TI), 256>>>(adj, out);
}

// round 3
// speedup vs baseline: 3.0630x; 3.0630x over previous
#include <cuda_runtime.h>
#include <cstdint>

#define NN   4096
#define FIN  128
#define NH   8
#define FO   64
#define FTOT 512
#define KT   32
#define NKT  (NN / KT)
#define LOG2E 1.4426950408889634f

// ---------------- scratch (static device memory only) ----------------
__device__ float g_ht[NN * FTOT];              // 8 MB: hW flat == ht[h][n][o]
__device__ float g_src[NH * NN];
__device__ float g_tgt[NH * NN];
__device__ float g_T[NH];                      // per-head global max of tgt
__device__ unsigned int g_adjb[NN * NN / 32];  // 2 MB bit-packed adjacency

// ---------------- kernel A: hW = h @ W ----------------
__global__ void k_gemm(const float* __restrict__ H, const float* __restrict__ W) {
    __shared__ float sA[32][FIN + 4];
    __shared__ float sW[FIN][64];
    const int rt = blockIdx.x, ct = blockIdx.y, t = threadIdx.x;
    const int row0 = rt * 32, col0 = ct * 64;

    const float4* Hv = (const float4*)(H + (size_t)row0 * FIN);
#pragma unroll
    for (int s = 0; s < 4; ++s) {
        int idx = t + 256 * s;
        float4 v = Hv[idx];
        int r = idx >> 5, q = idx & 31;
        sA[r][q * 4 + 0] = v.x; sA[r][q * 4 + 1] = v.y;
        sA[r][q * 4 + 2] = v.z; sA[r][q * 4 + 3] = v.w;
    }
#pragma unroll
    for (int s = 0; s < 8; ++s) {
        int idx = t + 256 * s;
        int k = idx >> 4, q = idx & 15;
        float4 v = *(const float4*)(W + (size_t)k * FTOT + col0 + q * 4);
        *(float4*)&sW[k][q * 4] = v;
    }
    __syncthreads();

    const int r = t >> 3;
    const int c0 = (t & 7) * 8;
    float acc[8];
#pragma unroll
    for (int c = 0; c < 8; ++c) acc[c] = 0.f;
#pragma unroll
    for (int k = 0; k < FIN; ++k) {
        float av = sA[r][k];
#pragma unroll
        for (int c = 0; c < 8; ++c) acc[c] = fmaf(av, sW[k][c0 + c], acc[c]);
    }
    float* outp = g_ht + (size_t)(row0 + r) * FTOT + col0 + c0;
    *(float4*)(outp)     = make_float4(acc[0], acc[1], acc[2], acc[3]);
    *(float4*)(outp + 4) = make_float4(acc[4], acc[5], acc[6], acc[7]);
}

// ---------------- kernel B: src/tgt projections ----------------
__global__ void k_srctgt(const float* __restrict__ a) {
    const int warp = threadIdx.x >> 5, lane = threadIdx.x & 31;
    const int gw = blockIdx.x * 8 + warp;
    const int h = gw >> 12;
    const int n = gw & (NN - 1);
    const float* htp = g_ht + (size_t)h * (NN * FO) + (size_t)n * FO;
    float v0 = htp[lane], v1 = htp[lane + 32];
    float a0 = a[h * 128 + lane],      a1 = a[h * 128 + lane + 32];
    float b0 = a[h * 128 + 64 + lane], b1 = a[h * 128 + 96 + lane];
    float s  = v0 * a0 + v1 * a1;
    float tg = v0 * b0 + v1 * b1;
#pragma unroll
    for (int off = 16; off; off >>= 1) {
        s  += __shfl_down_sync(0xFFFFFFFFu, s, off);
        tg += __shfl_down_sync(0xFFFFFFFFu, tg, off);
    }
    if (lane == 0) {
        g_src[h * NN + n] = s;
        g_tgt[h * NN + n] = tg;
    }
}

// ---------------- per-head global max of tgt ----------------
__global__ void k_redmax() {
    const int h = blockIdx.x, t = threadIdx.x;
    float mx = -1e30f;
    for (int n = t; n < NN; n += 256) mx = fmaxf(mx, g_tgt[h * NN + n]);
    __shared__ float sm[256];
    sm[t] = mx;
    __syncthreads();
    for (int s = 128; s > 0; s >>= 1) {
        if (t < s) sm[t] = fmaxf(sm[t], sm[t + s]);
        __syncthreads();
    }
    if (t == 0) g_T[h] = sm[0];
}

// ---------------- bit-pack adjacency ----------------
__global__ void k_pack(const int* __restrict__ adj) {
    const int lane = threadIdx.x & 31;
    const int gw = (blockIdx.x * blockDim.x + threadIdx.x) >> 5;
    const int nwarps = (gridDim.x * blockDim.x) >> 5;
    const int NW = NN * NN / 32;
    for (int w = gw; w < NW; w += nwarps) {
        int v = adj[(size_t)w * 32 + lane];
        unsigned m = __ballot_sync(0xFFFFFFFFu, v != 0);
        if (lane == 0) g_adjb[w] = m;
    }
}

// ---------------- tf32 helpers ----------------
__device__ __forceinline__ uint32_t f2tf32(float v) {
    uint32_t u;
    asm("cvt.rna.tf32.f32 %0, %1;" : "=r"(u) : "f"(v));
    return u;
}
__device__ __forceinline__ float ex2f(float x) {
    float r;
    asm("ex2.approx.f32 %0, %1;" : "=f"(r) : "f"(x));
    return r;
}
__device__ __forceinline__ void mma_tf32(float c[4], uint32_t a0, uint32_t a1,
                                         uint32_t a2, uint32_t a3,
                                         uint32_t b0, uint32_t b1) {
    asm volatile(
        "mma.sync.aligned.m16n8k8.row.col.f32.tf32.tf32.f32 "
        "{%0,%1,%2,%3}, {%4,%5,%6,%7}, {%8,%9}, {%0,%1,%2,%3};"
        : "+f"(c[0]), "+f"(c[1]), "+f"(c[2]), "+f"(c[3])
        : "r"(a0), "r"(a1), "r"(a2), "r"(a3), "r"(b0), "r"(b1));
}

// ---------------- kernel C: fused masked-softmax @ V  (mma.sync tf32) ----------------
// block = (head, 128-row i-tile). 8 warps, warp w owns rows w*16..w*16+15.
// A fragments (P weights) computed in registers; B = V tile (32k x 64n) in SMEM,
// row stride 72 words -> conflict-free fragment loads. Double-buffered over K.
__global__ void __launch_bounds__(256)
k_attn_mma(const unsigned int* __restrict__ adjb, float* __restrict__ out) {
    __shared__ float sV[2][KT][72];
    __shared__ float sTgt[2][KT];

    const int head  = blockIdx.x;
    const int ibase = blockIdx.y * 128;
    const int t     = threadIdx.x;
    const int wid   = t >> 5;
    const int lane  = t & 31;
    const int g     = lane >> 2;      // 0..7
    const int tg4   = lane & 3;       // 0..3

    const int r1 = wid * 16 + g;      // local row of a0/a2
    const int r2 = r1 + 8;            // local row of a1/a3

    const float src1 = g_src[head * NN + ibase + r1];
    const float src2 = g_src[head * NN + ibase + r2];
    const float Th   = g_T[head];
    const float e01 = src1 + Th, e02 = src2 + Th;
    const float m1 = fmaxf(e01, 0.2f * e01) * LOG2E;   // >= row max (scaled)
    const float m2 = fmaxf(e02, 0.2f * e02) * LOG2E;

    const unsigned int* arow1 = adjb + (size_t)(ibase + r1) * (NN / 32);
    const unsigned int* arow2 = adjb + (size_t)(ibase + r2) * (NN / 32);
    const float* tgtp = g_tgt + head * NN;
    const float* vp   = g_ht + (size_t)head * (NN * FO);   // V[j][o], contiguous o

    float acc[8][4];
#pragma unroll
    for (int nb = 0; nb < 8; ++nb)
#pragma unroll
        for (int q = 0; q < 4; ++q) acc[nb][q] = 0.f;
    float psum1 = 0.f, psum2 = 0.f;

    // ---- tile loader (tf32-rounded V + raw tgt chunk) ----
    auto load_tile = [&](int kt, int s) {
#pragma unroll
        for (int u = 0; u < 2; ++u) {
            int idx = t + u * 256;            // 512 float4 per tile
            int k = idx >> 4, q = idx & 15;
            float4 v = *(const float4*)(vp + (size_t)(kt * KT + k) * FO + q * 4);
            uint4 r;
            r.x = f2tf32(v.x); r.y = f2tf32(v.y);
            r.z = f2tf32(v.z); r.w = f2tf32(v.w);
            *(uint4*)&sV[s][k][q * 4] = r;
        }
        if (t < KT) sTgt[s][t] = tgtp[kt * KT + t];
    };

    load_tile(0, 0);

    for (int kt = 0; kt < NKT; ++kt) {
        const int s = kt & 1;
        __syncthreads();                       // tile kt ready; buf s^1 free
        if (kt + 1 < NKT) load_tile(kt + 1, s ^ 1);

        const unsigned int wa = arow1[kt];
        const unsigned int wb = arow2[kt];

#pragma unroll
        for (int ks = 0; ks < 4; ++ks) {
            const int c1 = ks * 8 + tg4;
            const int c2 = c1 + 4;
            const float tgv1 = sTgt[s][c1];
            const float tgv2 = sTgt[s][c2];

            // A fragment: 4 exps, masked, tf32-rounded
            float e, l, w0f, w1f, w2f, w3f;
            e = src1 + tgv1; l = fmaxf(e, 0.2f * e);
            w0f = ((wa >> c1) & 1u) ? ex2f(fmaf(l, LOG2E, -m1)) : 0.f;
            e = src2 + tgv1; l = fmaxf(e, 0.2f * e);
            w1f = ((wb >> c1) & 1u) ? ex2f(fmaf(l, LOG2E, -m2)) : 0.f;
            e = src1 + tgv2; l = fmaxf(e, 0.2f * e);
            w2f = ((wa >> c2) & 1u) ? ex2f(fmaf(l, LOG2E, -m1)) : 0.f;
            e = src2 + tgv2; l = fmaxf(e, 0.2f * e);
            w3f = ((wb >> c2) & 1u) ? ex2f(fmaf(l, LOG2E, -m2)) : 0.f;

            uint32_t a0 = f2tf32(w0f), a1 = f2tf32(w1f);
            uint32_t a2 = f2tf32(w2f), a3 = f2tf32(w3f);
            psum1 += __uint_as_float(a0) + __uint_as_float(a2);
            psum2 += __uint_as_float(a1) + __uint_as_float(a3);

            const int kr0 = ks * 8 + tg4;
#pragma unroll
            for (int nb = 0; nb < 8; ++nb) {
                uint32_t b0 = __float_as_uint(sV[s][kr0][nb * 8 + g]);
                uint32_t b1 = __float_as_uint(sV[s][kr0 + 4][nb * 8 + g]);
                mma_tf32(acc[nb], a0, a1, a2, a3, b0, b1);
            }
        }
    }

    // ---- row sums: reduce across the 4 lanes sharing each row ----
    psum1 += __shfl_xor_sync(0xFFFFFFFFu, psum1, 1);
    psum1 += __shfl_xor_sync(0xFFFFFFFFu, psum1, 2);
    psum2 += __shfl_xor_sync(0xFFFFFFFFu, psum2, 1);
    psum2 += __shfl_xor_sync(0xFFFFFFFFu, psum2, 2);
    const float inv1 = (psum1 > 0.f) ? 1.0f / psum1 : 0.f;
    const float inv2 = (psum2 > 0.f) ? 1.0f / psum2 : 0.f;

    // ---- store: d0,d1 -> (r1, 2*tg4 .. +1); d2,d3 -> (r2, ...) ----
    float* op1 = out + ((size_t)head * NN + ibase + r1) * FO + 2 * tg4;
    float* op2 = out + ((size_t)head * NN + ibase + r2) * FO + 2 * tg4;
#pragma unroll
    for (int nb = 0; nb < 8; ++nb) {
        float2 v1 = make_float2(acc[nb][0] * inv1, acc[nb][1] * inv1);
        float2 v2 = make_float2(acc[nb][2] * inv2, acc[nb][3] * inv2);
        *(float2*)(op1 + nb * 8) = v1;
        *(float2*)(op2 + nb * 8) = v2;
    }
}

// ---------------- host launcher ----------------
extern "C" void kernel_launch(void* const* d_in, const int* in_sizes, int n_in,
                              void* d_out, int out_size) {
    const float* H = nullptr; const int* adj = nullptr;
    const float* W = nullptr; const float* a = nullptr;
    for (int i = 0; i < n_in; ++i) {
        switch (in_sizes[i]) {
            case NN * FIN:    H   = (const float*)d_in[i]; break;
            case NN * NN:     adj = (const int*)d_in[i];   break;
            case FIN * FTOT:  W   = (const float*)d_in[i]; break;
            case NH * 2 * FO: a   = (const float*)d_in[i]; break;
        }
    }
    float* out = (float*)d_out;

    unsigned int* adjb; cudaGetSymbolAddress((void**)&adjb, g_adjb);

    k_gemm    <<<dim3(128, 8), 256>>>(H, W);
    k_pack    <<<512, 256>>>(adj);
    k_srctgt  <<<(NN * NH) / 8, 256>>>(a);
    k_redmax  <<<NH, 256>>>();
    k_attn_mma<<<dim3(NH, NN / 128), 256>>>(adjb, out);
}